// round 1
// baseline (speedup 1.0000x reference)
#include <cuda_runtime.h>

#define BB 4
#define TT 2048
#define CC 768
#define NROW (BB*TT)                  // 8192
#define NE   (BB*TT*CC)               // 6291456

// ---------------- scratch (static device globals; no allocs) ----------------
__device__ float g_X  [NE];
__device__ float g_Pi [NE];
__device__ float g_bX [NE];
__device__ float g_bPi[NE];
__device__ float g_Xn [NE];
__device__ float g_E  [(size_t)BB*TT*TT];   // 64 MB
__device__ float g_a  [NROW];
__device__ float g_z  [NROW];
__device__ float g_s  [NROW];

// ---------------- helpers ----------------
__device__ __forceinline__ float blockSum256(float v) {
    __shared__ float red[8];
    int tid = threadIdx.x;
    #pragma unroll
    for (int o = 16; o; o >>= 1) v += __shfl_xor_sync(0xffffffffu, v, o);
    if ((tid & 31) == 0) red[tid >> 5] = v;
    __syncthreads();
    if (tid == 0) {
        float s = 0.f;
        #pragma unroll
        for (int i = 0; i < 8; i++) s += red[i];
        red[0] = s;
    }
    __syncthreads();
    float r = red[0];
    __syncthreads();   // allow reuse of red on a second call
    return r;
}

__device__ __forceinline__ float t_of(const int* kp, float toff) {
    return 1.0f + (float)(*kp) + toff;   // T0=1, H_STEP=1
}

// ---------------- init: X=bX=Xk ; Pi=bPi=Lam(tk)*Pk ----------------
__global__ void k_init(const float* __restrict__ Xk, const float* __restrict__ Pk,
                       const int* __restrict__ kp,
                       float* __restrict__ X, float* __restrict__ Pi,
                       float* __restrict__ bX, float* __restrict__ bPi) {
    int i = blockIdx.x * 256 + threadIdx.x;
    float t = t_of(kp, 0.0f);
    float Lam = t * t * t;
    float x = Xk[i], p = Lam * Pk[i];
    X[i] = x; bX[i] = x; Pi[i] = p; bPi[i] = p;
}

// ---------------- LayerNorm (optionally scale input by lam(t)) ----------------
__global__ void k_ln(const float* __restrict__ Xin, const float* __restrict__ w,
                     float* __restrict__ out, const int* __restrict__ kp,
                     int scale_mode, float toff) {
    int row = blockIdx.x, tid = threadIdx.x;
    float scale = 1.0f;
    if (scale_mode) { float t = t_of(kp, toff); scale = 1.0f / (t * t * t); }
    const float* x = Xin + (size_t)row * CC;
    float v[3], s = 0.f;
    #pragma unroll
    for (int i = 0; i < 3; i++) { v[i] = scale * x[tid + 256 * i]; s += v[i]; }
    s = blockSum256(s);
    float mean = s * (1.0f / CC);
    float q = 0.f;
    #pragma unroll
    for (int i = 0; i < 3; i++) { float d = v[i] - mean; q += d * d; }
    q = blockSum256(q);
    float rstd = rsqrtf(q * (1.0f / CC) + 1e-5f);
    float* y = out + (size_t)row * CC;
    #pragma unroll
    for (int i = 0; i < 3; i++) { int c = tid + 256 * i; y[c] = (v[i] - mean) * rstd * w[c]; }
}

// ---------------- a[row] = sum Pin^2 (lam^2 applied later) ----------------
__global__ void k_rowsq(const float* __restrict__ Pin, float* __restrict__ a) {
    int row = blockIdx.x, tid = threadIdx.x;
    const float* p = Pin + (size_t)row * CC;
    float s = 0.f;
    #pragma unroll
    for (int i = 0; i < 3; i++) { float v = p[tid + 256 * i]; s += v * v; }
    s = blockSum256(s);
    if (tid == 0) a[row] = s;
}

// ---------------- gram: E[t,s] = exp(clip(Xn_t . Xn_s / 96)) for s<=t ----------------
__global__ void k_gram(const float* __restrict__ Xn, float* __restrict__ E) {
    int bs = blockIdx.x, bt = blockIdx.y;
    if (bs > bt) return;                         // strictly-above-diagonal tiles never read
    int b = blockIdx.z;
    const float* Xb = Xn + (size_t)b * TT * CC;
    int t0 = bt * 64, s0 = bs * 64;
    __shared__ float As[64][17];
    __shared__ float Bs[64][17];
    int tid = threadIdx.x;
    int tx = tid & 15, ty = tid >> 4;
    int lr = tid >> 2, lc = (tid & 3) * 4;
    float acc[4][4] = {};
    for (int kk = 0; kk < CC; kk += 16) {
        #pragma unroll
        for (int j = 0; j < 4; j++) {
            As[lr][lc + j] = Xb[(size_t)(t0 + lr) * CC + kk + lc + j];
            Bs[lr][lc + j] = Xb[(size_t)(s0 + lr) * CC + kk + lc + j];
        }
        __syncthreads();
        #pragma unroll
        for (int k = 0; k < 16; k++) {
            float ar[4], br[4];
            #pragma unroll
            for (int i = 0; i < 4; i++) ar[i] = As[ty * 4 + i][k];
            #pragma unroll
            for (int j = 0; j < 4; j++) br[j] = Bs[tx * 4 + j][k];
            #pragma unroll
            for (int i = 0; i < 4; i++)
                #pragma unroll
                for (int j = 0; j < 4; j++) acc[i][j] += ar[i] * br[j];
        }
        __syncthreads();
    }
    float* Eb = E + (size_t)b * TT * TT;
    #pragma unroll
    for (int i = 0; i < 4; i++) {
        int t = t0 + ty * 4 + i;
        #pragma unroll
        for (int j = 0; j < 4; j++) {
            int s = s0 + tx * 4 + j;
            float e = 0.f;
            if (s <= t) {
                float S = acc[i][j] * (1.0f / 96.0f);
                S = fminf(fmaxf(S, -60.f), 60.f);
                e = __expf(S);
            }
            Eb[(size_t)t * TT + s] = e;
        }
    }
}

// ---------------- z = max(rowsum(E)/T, eps); s = lam^2 * a / (z^2+eps) ----------------
__global__ void k_zs(const float* __restrict__ E, const float* __restrict__ a,
                     const int* __restrict__ kp, float toff,
                     float* __restrict__ z, float* __restrict__ s) {
    int row = blockIdx.x;
    int b = row / TT, t = row % TT;
    const float* Er = E + (size_t)b * TT * TT + (size_t)t * TT;
    int tid = threadIdx.x;
    float acc = 0.f;
    for (int i = tid; i <= t; i += 256) acc += Er[i];
    acc = blockSum256(acc);
    if (tid == 0) {
        float tv = t_of(kp, toff);
        float lam = 1.0f / (tv * tv * tv);
        float zz = fmaxf(acc * (1.0f / TT), 1e-8f);
        z[row] = zz;
        s[row] = (lam * lam * a[row]) / (zz * zz + 1e-8f);
    }
}

// ---------------- force: Pupd += tau*Lam/(2T) * (E .* (s_t+s_s-2)) @ Xn ----------------
__global__ void k_force(const float* __restrict__ E, const float* __restrict__ Xn,
                        const float* __restrict__ sv, const int* __restrict__ kp, float toff,
                        float* __restrict__ Pupd) {
    int b = blockIdx.z, bt = blockIdx.y, bc = blockIdx.x;
    int t0 = bt * 64, c0 = bc * 64;
    const float* Eb = E + (size_t)b * TT * TT;
    const float* Xb = Xn + (size_t)b * TT * CC;
    const float* sb = sv + b * TT;
    __shared__ float As[64][17];
    __shared__ float Bs[16][65];
    int tid = threadIdx.x;
    int tx = tid & 15, ty = tid >> 4;
    int ar_ = tid >> 2, ac_ = (tid & 3) * 4;     // A loader: row 0..63, col 0..12
    int br_ = tid >> 4, bc_ = (tid & 15) * 4;    // B loader: row 0..15, col 0..60
    float sA = sb[t0 + ar_];
    float acc[4][4] = {};
    int kmax = t0 + 64;                          // causal: s < t0+64
    for (int ss0 = 0; ss0 < kmax; ss0 += 16) {
        #pragma unroll
        for (int j = 0; j < 4; j++) {
            float e = Eb[(size_t)(t0 + ar_) * TT + ss0 + ac_ + j];
            As[ar_][ac_ + j] = e * (sA + sb[ss0 + ac_ + j] - 2.0f);
            Bs[br_][bc_ + j] = Xb[(size_t)(ss0 + br_) * CC + c0 + bc_ + j];
        }
        __syncthreads();
        #pragma unroll
        for (int k = 0; k < 16; k++) {
            float ar4[4], br4[4];
            #pragma unroll
            for (int i = 0; i < 4; i++) ar4[i] = As[ty * 4 + i][k];
            #pragma unroll
            for (int j = 0; j < 4; j++) br4[j] = Bs[k][tx * 4 + j];
            #pragma unroll
            for (int i = 0; i < 4; i++)
                #pragma unroll
                for (int j = 0; j < 4; j++) acc[i][j] += ar4[i] * br4[j];
        }
        __syncthreads();
    }
    float tv = t_of(kp, toff);
    float Lam = tv * tv * tv;
    float coef = 0.5f * Lam / (2.0f * TT);       // tau * Lam / (2T)
    #pragma unroll
    for (int i = 0; i < 4; i++)
        #pragma unroll
        for (int j = 0; j < 4; j++)
            Pupd[((size_t)b * TT + t0 + ty * 4 + i) * CC + c0 + tx * 4 + j] += coef * acc[i][j];
}

// ---------------- vel: Xupd += tau * lam * Pin / z[row] ----------------
__global__ void k_vel(const float* __restrict__ Pin, const float* __restrict__ z,
                      const int* __restrict__ kp, float toff, float* __restrict__ Xupd) {
    int i = blockIdx.x * 256 + threadIdx.x;
    float tv = t_of(kp, toff);
    float lam = 1.0f / (tv * tv * tv);
    int row = i / CC;
    Xupd[i] += 0.5f * lam * Pin[i] / z[row];
}

// ---------------- rotation mixing, theta = 2 ----------------
__global__ void k_rotate(float* __restrict__ X, float* __restrict__ Pi,
                         float* __restrict__ bX, float* __restrict__ bPi) {
    int i = blockIdx.x * 256 + threadIdx.x;
    const float c  = -0.41614683654714241f;   // cos(2)
    const float sn =  0.90929742682568170f;   // sin(2)
    float x = X[i], p = Pi[i], bx = bX[i], bp = bPi[i];
    float dX = x - bx, dP = p - bp, sX = x + bx, sP = p + bp;
    X[i]   = 0.5f * (sX + c * dX + sn * dP);
    Pi[i]  = 0.5f * (sP - sn * dX + c * dP);
    bX[i]  = 0.5f * (sX - c * dX - sn * dP);
    bPi[i] = 0.5f * (sP + sn * dX - c * dP);
}

__global__ void k_copy(const float* __restrict__ src, float* __restrict__ dst) {
    int i = blockIdx.x * 256 + threadIdx.x;
    dst[i] = src[i];
}

// ---------------- launch ----------------
extern "C" void kernel_launch(void* const* d_in, const int* in_sizes, int n_in,
                              void* d_out, int out_size) {
    const float* Xk     = (const float*)d_in[0];
    const float* Pk     = (const float*)d_in[1];
    const float* ln_w   = (const float*)d_in[2];
    const float* ln_v_w = (const float*)d_in[3];
    const int*   kp     = (const int*)  d_in[4];
    float* out = (float*)d_out;

    float *X, *Pi, *bX, *bPi, *Xn, *E, *a, *z, *s;
    cudaGetSymbolAddress((void**)&X,   g_X);
    cudaGetSymbolAddress((void**)&Pi,  g_Pi);
    cudaGetSymbolAddress((void**)&bX,  g_bX);
    cudaGetSymbolAddress((void**)&bPi, g_bPi);
    cudaGetSymbolAddress((void**)&Xn,  g_Xn);
    cudaGetSymbolAddress((void**)&E,   g_E);
    cudaGetSymbolAddress((void**)&a,   g_a);
    cudaGetSymbolAddress((void**)&z,   g_z);
    cudaGetSymbolAddress((void**)&s,   g_s);

    const int EB = NE / 256;   // elementwise grid

    k_init<<<EB, 256>>>(Xk, Pk, kp, X, Pi, bX, bPi);

    auto phase = [&](const float* Xin, const float* Pin, float* Xupd, float* Pupd,
                     float toff, bool dovel) {
        k_ln   <<<NROW, 256>>>(Xin, ln_w, Xn, kp, 0, 0.f);
        k_rowsq<<<NROW, 256>>>(Pin, a);
        k_gram <<<dim3(32, 32, BB), 256>>>(Xn, E);
        k_zs   <<<NROW, 256>>>(E, a, kp, toff, z, s);
        k_force<<<dim3(12, 32, BB), 256>>>(E, Xn, s, kp, toff, Pupd);
        if (dovel) k_vel<<<EB, 256>>>(Pin, z, kp, toff, Xupd);
    };

    phase(X,  bPi, bX, Pi,  0.0f, true);   // first half kick/drift (t = tk)
    phase(bX, Pi,  X,  bPi, 0.5f, true);   // (t = tk + tau)
    k_rotate<<<EB, 256>>>(X, Pi, bX, bPi);
    phase(bX, Pi,  X,  bPi, 0.5f, true);   // second half (t = bar_t = tk + tau)
    phase(X,  bPi, bX, Pi,  1.0f, false);  // (t = tk + 2*tau); bar_X vel is dead -> skipped

    k_copy<<<EB, 256>>>(X, out);
    k_ln  <<<NROW, 256>>>(Pi, ln_v_w, out + NE, kp, 1, 1.0f);  // Pk1 = LN(lam(tk1)*Pi)
}

// round 2
// speedup vs baseline: 1.6280x; 1.6280x over previous
#include <cuda_runtime.h>

#define BB 4
#define TT 2048
#define CC 768
#define NROW (BB*TT)                  // 8192
#define NE   (BB*TT*CC)               // 6291456

// ---------------- scratch (static device globals; no allocs) ----------------
__device__ float g_X  [NE];
__device__ float g_Pi [NE];
__device__ float g_bX [NE];
__device__ float g_bPi[NE];
__device__ float g_Xn [NE];
__device__ float g_E  [(size_t)BB*TT*TT];   // 64 MB
__device__ float g_a  [NROW];
__device__ float g_z  [NROW];
__device__ float g_s  [NROW];

// ---------------- helpers ----------------
__device__ __forceinline__ float blockSum256(float v) {
    __shared__ float red[8];
    int tid = threadIdx.x;
    #pragma unroll
    for (int o = 16; o; o >>= 1) v += __shfl_xor_sync(0xffffffffu, v, o);
    if ((tid & 31) == 0) red[tid >> 5] = v;
    __syncthreads();
    if (tid == 0) {
        float s = 0.f;
        #pragma unroll
        for (int i = 0; i < 8; i++) s += red[i];
        red[0] = s;
    }
    __syncthreads();
    float r = red[0];
    __syncthreads();
    return r;
}

__device__ __forceinline__ float t_of(const int* kp, float toff) {
    return 1.0f + (float)(*kp) + toff;   // T0=1, H_STEP=1
}

// ---------------- init ----------------
__global__ void k_init(const float* __restrict__ Xk, const float* __restrict__ Pk,
                       const int* __restrict__ kp,
                       float* __restrict__ X, float* __restrict__ Pi,
                       float* __restrict__ bX, float* __restrict__ bPi) {
    int i = blockIdx.x * 256 + threadIdx.x;
    float t = t_of(kp, 0.0f);
    float Lam = t * t * t;
    float x = Xk[i], p = Lam * Pk[i];
    X[i] = x; bX[i] = x; Pi[i] = p; bPi[i] = p;
}

// ---------------- LayerNorm ----------------
__global__ void k_ln(const float* __restrict__ Xin, const float* __restrict__ w,
                     float* __restrict__ out, const int* __restrict__ kp,
                     int scale_mode, float toff) {
    int row = blockIdx.x, tid = threadIdx.x;
    float scale = 1.0f;
    if (scale_mode) { float t = t_of(kp, toff); scale = 1.0f / (t * t * t); }
    const float* x = Xin + (size_t)row * CC;
    float v[3], s = 0.f;
    #pragma unroll
    for (int i = 0; i < 3; i++) { v[i] = scale * x[tid + 256 * i]; s += v[i]; }
    s = blockSum256(s);
    float mean = s * (1.0f / CC);
    float q = 0.f;
    #pragma unroll
    for (int i = 0; i < 3; i++) { float d = v[i] - mean; q += d * d; }
    q = blockSum256(q);
    float rstd = rsqrtf(q * (1.0f / CC) + 1e-5f);
    float* y = out + (size_t)row * CC;
    #pragma unroll
    for (int i = 0; i < 3; i++) { int c = tid + 256 * i; y[c] = (v[i] - mean) * rstd * w[c]; }
}

// ---------------- rowsq ----------------
__global__ void k_rowsq(const float* __restrict__ Pin, float* __restrict__ a) {
    int row = blockIdx.x, tid = threadIdx.x;
    const float* p = Pin + (size_t)row * CC;
    float s = 0.f;
    #pragma unroll
    for (int i = 0; i < 3; i++) { float v = p[tid + 256 * i]; s += v * v; }
    s = blockSum256(s);
    if (tid == 0) a[row] = s;
}

// ---------------- gram: 128x128 tile, 8x8/thread, BK=8, double-buffered ----------------
__global__ __launch_bounds__(256, 2)
void k_gram(const float* __restrict__ Xn, float* __restrict__ E) {
    int bs = blockIdx.x, bt = blockIdx.y;
    if (bs > bt) return;
    int b = blockIdx.z;
    const float* Xb = Xn + (size_t)b * TT * CC;
    int t0 = bt << 7, s0 = bs << 7;
    __shared__ float As[8][132];
    __shared__ float Bs[8][132];
    int tid = threadIdx.x;
    int lr = tid >> 1, lk = (tid & 1) << 2;
    int tx = tid & 15, ty = tid >> 4;
    const float* ga = Xb + (size_t)(t0 + lr) * CC + lk;
    const float* gb = Xb + (size_t)(s0 + lr) * CC + lk;
    float4 ra = *(const float4*)ga;
    float4 rb = *(const float4*)gb;
    float acc[8][8] = {};
    for (int kk = 8; kk <= CC; kk += 8) {
        As[lk+0][lr] = ra.x; As[lk+1][lr] = ra.y; As[lk+2][lr] = ra.z; As[lk+3][lr] = ra.w;
        Bs[lk+0][lr] = rb.x; Bs[lk+1][lr] = rb.y; Bs[lk+2][lr] = rb.z; Bs[lk+3][lr] = rb.w;
        __syncthreads();
        if (kk < CC) { ra = *(const float4*)(ga + kk); rb = *(const float4*)(gb + kk); }
        #pragma unroll
        for (int k = 0; k < 8; k++) {
            float a[8], bb[8];
            *(float4*)&a[0]  = *(const float4*)&As[k][ty * 8];
            *(float4*)&a[4]  = *(const float4*)&As[k][ty * 8 + 4];
            *(float4*)&bb[0] = *(const float4*)&Bs[k][tx * 8];
            *(float4*)&bb[4] = *(const float4*)&Bs[k][tx * 8 + 4];
            #pragma unroll
            for (int i = 0; i < 8; i++)
                #pragma unroll
                for (int j = 0; j < 8; j++) acc[i][j] += a[i] * bb[j];
        }
        __syncthreads();
    }
    float* Eb = E + (size_t)b * TT * TT;
    bool full = bs < bt;
    #pragma unroll
    for (int i = 0; i < 8; i++) {
        int t = t0 + ty * 8 + i;
        float out[8];
        #pragma unroll
        for (int j = 0; j < 8; j++) {
            int s = s0 + tx * 8 + j;
            float e = 0.f;
            if (full || s <= t) {
                float S = acc[i][j] * (1.0f / 96.0f);
                S = fminf(fmaxf(S, -60.f), 60.f);
                e = __expf(S);
            }
            out[j] = e;
        }
        float* p = Eb + (size_t)t * TT + s0 + tx * 8;
        *(float4*)p       = *(const float4*)&out[0];
        *(float4*)(p + 4) = *(const float4*)&out[4];
    }
}

// ---------------- z, s ----------------
__global__ void k_zs(const float* __restrict__ E, const float* __restrict__ a,
                     const int* __restrict__ kp, float toff,
                     float* __restrict__ z, float* __restrict__ s) {
    int row = blockIdx.x;
    int b = row / TT, t = row % TT;
    const float* Er = E + (size_t)b * TT * TT + (size_t)t * TT;
    int tid = threadIdx.x;
    float acc = 0.f;
    for (int i = tid; i <= t; i += 256) acc += Er[i];
    acc = blockSum256(acc);
    if (tid == 0) {
        float tv = t_of(kp, toff);
        float lam = 1.0f / (tv * tv * tv);
        float zz = fmaxf(acc * (1.0f / TT), 1e-8f);
        z[row] = zz;
        s[row] = (lam * lam * a[row]) / (zz * zz + 1e-8f);
    }
}

// ---------------- force: 128x64 tile, 8x4/thread, BK=16, double-buffered ----------------
__global__ __launch_bounds__(256, 2)
void k_force(const float* __restrict__ E, const float* __restrict__ Xn,
             const float* __restrict__ sv, const int* __restrict__ kp, float toff,
             float* __restrict__ Pupd) {
    int b = blockIdx.z, bt = blockIdx.y, bc = blockIdx.x;
    int t0 = bt << 7, c0 = bc << 6;
    const float* Eb = E + (size_t)b * TT * TT;
    const float* Xb = Xn + (size_t)b * TT * CC;
    const float* sb = sv + b * TT;
    __shared__ float As[16][132];
    __shared__ float Bs[16][68];
    int tid = threadIdx.x;
    int ar = tid >> 2, ak = (tid & 3) << 2;
    int br = tid >> 4, bcol = (tid & 15) << 2;
    int tx = tid & 15, ty = tid >> 4;
    float sA0 = sb[t0 + ar] - 2.0f;
    float sA1 = sb[t0 + 64 + ar] - 2.0f;
    int kmax = t0 + 128;
    const float* gE0 = Eb + (size_t)(t0 + ar) * TT + ak;
    const float* gE1 = Eb + (size_t)(t0 + 64 + ar) * TT + ak;
    const float* gX  = Xb + (size_t)br * CC + c0 + bcol;
    float4 ea0 = *(const float4*)gE0;
    float4 ea1 = *(const float4*)gE1;
    float4 sc  = *(const float4*)(sb + ak);
    float4 xb  = *(const float4*)gX;
    float acc[8][4] = {};
    for (int ss = 16; ss <= kmax; ss += 16) {
        As[ak+0][ar]      = ea0.x * (sA0 + sc.x);
        As[ak+1][ar]      = ea0.y * (sA0 + sc.y);
        As[ak+2][ar]      = ea0.z * (sA0 + sc.z);
        As[ak+3][ar]      = ea0.w * (sA0 + sc.w);
        As[ak+0][ar+64]   = ea1.x * (sA1 + sc.x);
        As[ak+1][ar+64]   = ea1.y * (sA1 + sc.y);
        As[ak+2][ar+64]   = ea1.z * (sA1 + sc.z);
        As[ak+3][ar+64]   = ea1.w * (sA1 + sc.w);
        Bs[br][bcol+0] = xb.x; Bs[br][bcol+1] = xb.y;
        Bs[br][bcol+2] = xb.z; Bs[br][bcol+3] = xb.w;
        __syncthreads();
        if (ss < kmax) {
            ea0 = *(const float4*)(gE0 + ss);
            ea1 = *(const float4*)(gE1 + ss);
            sc  = *(const float4*)(sb + ss + ak);
            xb  = *(const float4*)(gX + (size_t)ss * CC);
        }
        #pragma unroll
        for (int k = 0; k < 16; k++) {
            float a[8], bb4[4];
            *(float4*)&a[0]   = *(const float4*)&As[k][ty * 8];
            *(float4*)&a[4]   = *(const float4*)&As[k][ty * 8 + 4];
            *(float4*)&bb4[0] = *(const float4*)&Bs[k][tx * 4];
            #pragma unroll
            for (int i = 0; i < 8; i++)
                #pragma unroll
                for (int j = 0; j < 4; j++) acc[i][j] += a[i] * bb4[j];
        }
        __syncthreads();
    }
    float tv = t_of(kp, toff);
    float coef = 0.25f * tv * tv * tv / TT;   // tau * Lam / (2T)
    #pragma unroll
    for (int i = 0; i < 8; i++) {
        float* p = Pupd + ((size_t)b * TT + t0 + ty * 8 + i) * CC + c0 + tx * 4;
        float4 v = *(float4*)p;
        v.x += coef * acc[i][0];
        v.y += coef * acc[i][1];
        v.z += coef * acc[i][2];
        v.w += coef * acc[i][3];
        *(float4*)p = v;
    }
}

// ---------------- vel ----------------
__global__ void k_vel(const float* __restrict__ Pin, const float* __restrict__ z,
                      const int* __restrict__ kp, float toff, float* __restrict__ Xupd) {
    int i = blockIdx.x * 256 + threadIdx.x;
    float tv = t_of(kp, toff);
    float lam = 1.0f / (tv * tv * tv);
    int row = i / CC;
    Xupd[i] += 0.5f * lam * Pin[i] / z[row];
}

// ---------------- rotation ----------------
__global__ void k_rotate(float* __restrict__ X, float* __restrict__ Pi,
                         float* __restrict__ bX, float* __restrict__ bPi) {
    int i = blockIdx.x * 256 + threadIdx.x;
    const float c  = -0.41614683654714241f;   // cos(2)
    const float sn =  0.90929742682568170f;   // sin(2)
    float x = X[i], p = Pi[i], bx = bX[i], bp = bPi[i];
    float dX = x - bx, dP = p - bp, sX = x + bx, sP = p + bp;
    X[i]   = 0.5f * (sX + c * dX + sn * dP);
    Pi[i]  = 0.5f * (sP - sn * dX + c * dP);
    bX[i]  = 0.5f * (sX - c * dX - sn * dP);
    bPi[i] = 0.5f * (sP + sn * dX - c * dP);
}

__global__ void k_copy(const float* __restrict__ src, float* __restrict__ dst) {
    int i = blockIdx.x * 256 + threadIdx.x;
    dst[i] = src[i];
}

// ---------------- launch ----------------
extern "C" void kernel_launch(void* const* d_in, const int* in_sizes, int n_in,
                              void* d_out, int out_size) {
    const float* Xk     = (const float*)d_in[0];
    const float* Pk     = (const float*)d_in[1];
    const float* ln_w   = (const float*)d_in[2];
    const float* ln_v_w = (const float*)d_in[3];
    const int*   kp     = (const int*)  d_in[4];
    float* out = (float*)d_out;

    float *X, *Pi, *bX, *bPi, *Xn, *E, *a, *z, *s;
    cudaGetSymbolAddress((void**)&X,   g_X);
    cudaGetSymbolAddress((void**)&Pi,  g_Pi);
    cudaGetSymbolAddress((void**)&bX,  g_bX);
    cudaGetSymbolAddress((void**)&bPi, g_bPi);
    cudaGetSymbolAddress((void**)&Xn,  g_Xn);
    cudaGetSymbolAddress((void**)&E,   g_E);
    cudaGetSymbolAddress((void**)&a,   g_a);
    cudaGetSymbolAddress((void**)&z,   g_z);
    cudaGetSymbolAddress((void**)&s,   g_s);

    const int EB = NE / 256;

    k_init<<<EB, 256>>>(Xk, Pk, kp, X, Pi, bX, bPi);

    auto phase = [&](const float* Xin, const float* Pin, float* Xupd, float* Pupd,
                     float toff, bool dovel) {
        k_ln   <<<NROW, 256>>>(Xin, ln_w, Xn, kp, 0, 0.f);
        k_rowsq<<<NROW, 256>>>(Pin, a);
        k_gram <<<dim3(16, 16, BB), 256>>>(Xn, E);
        k_zs   <<<NROW, 256>>>(E, a, kp, toff, z, s);
        k_force<<<dim3(12, 16, BB), 256>>>(E, Xn, s, kp, toff, Pupd);
        if (dovel) k_vel<<<EB, 256>>>(Pin, z, kp, toff, Xupd);
    };

    phase(X,  bPi, bX, Pi,  0.0f, true);
    phase(bX, Pi,  X,  bPi, 0.5f, true);
    k_rotate<<<EB, 256>>>(X, Pi, bX, bPi);
    phase(bX, Pi,  X,  bPi, 0.5f, true);
    phase(X,  bPi, bX, Pi,  1.0f, false);

    k_copy<<<EB, 256>>>(X, out);
    k_ln  <<<NROW, 256>>>(Pi, ln_v_w, out + NE, kp, 1, 1.0f);
}

// round 7
// speedup vs baseline: 3.1997x; 1.9654x over previous
#include <cuda_runtime.h>
#include <cstdint>

#define BB 4
#define TT 2048
#define CC 768
#define NROW (BB*TT)                  // 8192
#define NE   (BB*TT*CC)               // 6291456

// ---------------- scratch ----------------
__device__ float g_X  [NE];
__device__ float g_Pi [NE];
__device__ float g_bX [NE];
__device__ float g_bPi[NE];
__device__ float g_Xn [NE];
__device__ float g_XnT[NE];
__device__ float g_E  [(size_t)BB*TT*TT];   // 64 MB
__device__ float g_a  [NROW];
__device__ float g_z  [NROW];
__device__ float g_s  [NROW];
__device__ float g_part[(size_t)NROW*64];   // per-32-col row partials

// ---------------- PTX helpers ----------------
__device__ __forceinline__ uint32_t smem_u32(const void* p){
    uint32_t a; asm("{ .reg .u64 t; cvta.to.shared.u64 t, %1; cvt.u32.u64 %0, t; }" : "=r"(a) : "l"(p));
    return a;
}
#define CP16(dst, src) \
    asm volatile("cp.async.cg.shared.global [%0], [%1], 16;" :: "r"(dst), "l"(src) : "memory")
#define CP_COMMIT() asm volatile("cp.async.commit_group;" ::: "memory")
#define CP_WAIT1()  asm volatile("cp.async.wait_group 1;" ::: "memory")
#define CP_WAIT0()  asm volatile("cp.async.wait_group 0;" ::: "memory")

__device__ __forceinline__ uint32_t to_tf32(float f){
    uint32_t r; asm("cvt.rna.tf32.f32 %0, %1;" : "=r"(r) : "f"(f));
    return r;
}
__device__ __forceinline__ void mma_tf32(float* c, const uint32_t* a, const uint32_t* b){
    asm volatile(
        "mma.sync.aligned.m16n8k8.row.col.f32.tf32.tf32.f32 "
        "{%0,%1,%2,%3}, {%4,%5,%6,%7}, {%8,%9}, {%0,%1,%2,%3};"
        : "+f"(c[0]), "+f"(c[1]), "+f"(c[2]), "+f"(c[3])
        : "r"(a[0]), "r"(a[1]), "r"(a[2]), "r"(a[3]), "r"(b[0]), "r"(b[1]));
}

__device__ __forceinline__ float blockSum256(float v) {
    __shared__ float red[8];
    int tid = threadIdx.x;
    #pragma unroll
    for (int o = 16; o; o >>= 1) v += __shfl_xor_sync(0xffffffffu, v, o);
    if ((tid & 31) == 0) red[tid >> 5] = v;
    __syncthreads();
    if (tid == 0) {
        float s = 0.f;
        #pragma unroll
        for (int i = 0; i < 8; i++) s += red[i];
        red[0] = s;
    }
    __syncthreads();
    float r = red[0];
    __syncthreads();
    return r;
}
__device__ __forceinline__ float t_of(const int* kp, float toff) {
    return 1.0f + (float)(*kp) + toff;
}

// ---------------- init ----------------
__global__ void k_init(const float* __restrict__ Xk, const float* __restrict__ Pk,
                       const int* __restrict__ kp,
                       float* __restrict__ X, float* __restrict__ Pi,
                       float* __restrict__ bX, float* __restrict__ bPi) {
    int i = blockIdx.x * 256 + threadIdx.x;
    float t = t_of(kp, 0.0f);
    float Lam = t * t * t;
    float x = Xk[i], p = Lam * Pk[i];
    X[i] = x; bX[i] = x; Pi[i] = p; bPi[i] = p;
}

// ---------------- LayerNorm (round_out: emit tf32-rounded values) ----------------
__global__ void k_ln(const float* __restrict__ Xin, const float* __restrict__ w,
                     float* __restrict__ out, const int* __restrict__ kp,
                     int scale_mode, float toff, int round_out) {
    int row = blockIdx.x, tid = threadIdx.x;
    float scale = 1.0f;
    if (scale_mode) { float t = t_of(kp, toff); scale = 1.0f / (t * t * t); }
    const float* x = Xin + (size_t)row * CC;
    float v[3], s = 0.f;
    #pragma unroll
    for (int i = 0; i < 3; i++) { v[i] = scale * x[tid + 256 * i]; s += v[i]; }
    s = blockSum256(s);
    float mean = s * (1.0f / CC);
    float q = 0.f;
    #pragma unroll
    for (int i = 0; i < 3; i++) { float d = v[i] - mean; q += d * d; }
    q = blockSum256(q);
    float rstd = rsqrtf(q * (1.0f / CC) + 1e-5f);
    float* y = out + (size_t)row * CC;
    #pragma unroll
    for (int i = 0; i < 3; i++) {
        int c = tid + 256 * i;
        float val = (v[i] - mean) * rstd * w[c];
        if (round_out) val = __uint_as_float(to_tf32(val));
        y[c] = val;
    }
}

// ---------------- rowsq ----------------
__global__ void k_rowsq(const float* __restrict__ Pin, float* __restrict__ a) {
    int row = blockIdx.x, tid = threadIdx.x;
    const float* p = Pin + (size_t)row * CC;
    float s = 0.f;
    #pragma unroll
    for (int i = 0; i < 3; i++) { float v = p[tid + 256 * i]; s += v * v; }
    s = blockSum256(s);
    if (tid == 0) a[row] = s;
}

// ---------------- transpose Xn -> XnT [b][C][T] ----------------
__global__ void k_transpose(const float* __restrict__ Xn, float* __restrict__ XnT) {
    __shared__ float tile[32][33];
    int b = blockIdx.z;
    int c0 = blockIdx.x * 32, s0 = blockIdx.y * 32;
    int tx = threadIdx.x, ty = threadIdx.y;
    const float* src = Xn + (size_t)b * TT * CC;
    #pragma unroll
    for (int g = 0; g < 32; g += 8)
        tile[ty + g][tx] = src[(size_t)(s0 + ty + g) * CC + c0 + tx];
    __syncthreads();
    float* dst = XnT + (size_t)b * CC * TT;
    #pragma unroll
    for (int g = 0; g < 32; g += 8)
        dst[(size_t)(c0 + ty + g) * TT + s0 + tx] = tile[tx][ty + g];
}

// ================= gram via mma.sync tf32 =================
// block 256 thr (8 warps), tile 128x128, warp tile 64x32, BK=16
__global__ __launch_bounds__(256, 2)
void k_gram_mma(const float* __restrict__ Xn, float* __restrict__ E, float* __restrict__ part) {
    int bs = blockIdx.x, bt = blockIdx.y;
    if (bs > bt) return;
    int b = blockIdx.z;
    __shared__ float As[2][128 * 20];
    __shared__ float Bs[2][128 * 20];
    int tid = threadIdx.x, wid = tid >> 5, lane = tid & 31;
    int g = lane >> 2, q = lane & 3;
    int warpM = wid & 1, warpN = wid >> 1;
    int t0 = bt << 7, s0 = bs << 7;
    const float* gA = Xn + ((size_t)b * TT + t0) * CC;
    const float* gB = Xn + ((size_t)b * TT + s0) * CC;
    uint32_t asu = smem_u32(&As[0][0]);
    uint32_t bsu = smem_u32(&Bs[0][0]);

    int lr0 = tid >> 2, lc0 = (tid & 3) << 2;
    int lr1 = (tid + 256) >> 2, lc1 = lc0;

    float acc[4][4][4];
    #pragma unroll
    for (int i = 0; i < 4; i++)
        #pragma unroll
        for (int j = 0; j < 4; j++)
            #pragma unroll
            for (int r = 0; r < 4; r++) acc[i][j][r] = 0.f;

    const int NIT = CC / 16;   // 48
    // prologue
    {
        CP16(asu + (uint32_t)(lr0 * 20 + lc0) * 4, gA + (size_t)lr0 * CC + lc0);
        CP16(asu + (uint32_t)(lr1 * 20 + lc1) * 4, gA + (size_t)lr1 * CC + lc1);
        CP16(bsu + (uint32_t)(lr0 * 20 + lc0) * 4, gB + (size_t)lr0 * CC + lc0);
        CP16(bsu + (uint32_t)(lr1 * 20 + lc1) * 4, gB + (size_t)lr1 * CC + lc1);
        CP_COMMIT();
    }
    for (int i = 0; i < NIT; i++) {
        int st = i & 1;
        if (i + 1 < NIT) {
            int kk = (i + 1) * 16;
            uint32_t so = (uint32_t)((i + 1) & 1) * 10240;
            CP16(asu + so + (uint32_t)(lr0 * 20 + lc0) * 4, gA + (size_t)lr0 * CC + kk + lc0);
            CP16(asu + so + (uint32_t)(lr1 * 20 + lc1) * 4, gA + (size_t)lr1 * CC + kk + lc1);
            CP16(bsu + so + (uint32_t)(lr0 * 20 + lc0) * 4, gB + (size_t)lr0 * CC + kk + lc0);
            CP16(bsu + so + (uint32_t)(lr1 * 20 + lc1) * 4, gB + (size_t)lr1 * CC + kk + lc1);
            CP_COMMIT();
            CP_WAIT1();
        } else {
            CP_WAIT0();
        }
        __syncthreads();
        const float* as = &As[st][0];
        const float* bsm = &Bs[st][0];
        #pragma unroll
        for (int ks = 0; ks < 2; ks++) {
            int kb = ks * 8 + q;
            uint32_t bf[4][2];
            #pragma unroll
            for (int nt = 0; nt < 4; nt++) {
                int n = warpN * 32 + nt * 8 + g;
                bf[nt][0] = __float_as_uint(bsm[n * 20 + kb]);
                bf[nt][1] = __float_as_uint(bsm[n * 20 + kb + 4]);
            }
            #pragma unroll
            for (int mt = 0; mt < 4; mt++) {
                int m = warpM * 64 + mt * 16 + g;
                uint32_t af[4];
                af[0] = __float_as_uint(as[m * 20 + kb]);
                af[1] = __float_as_uint(as[(m + 8) * 20 + kb]);
                af[2] = __float_as_uint(as[m * 20 + kb + 4]);
                af[3] = __float_as_uint(as[(m + 8) * 20 + kb + 4]);
                #pragma unroll
                for (int nt = 0; nt < 4; nt++) mma_tf32(acc[mt][nt], af, bf[nt]);
            }
        }
        __syncthreads();
    }

    // epilogue: clip/exp/mask, store E, fused row partial sums (32-col granularity per warp)
    bool diag = (bs == bt);
    float* Eb = E + (size_t)b * TT * TT;
    float rowsum[8];
    #pragma unroll
    for (int mt = 0; mt < 4; mt++) {
        #pragma unroll
        for (int rr = 0; rr < 2; rr++) {
            int row = warpM * 64 + mt * 16 + rr * 8 + g;
            int tglob = t0 + row;
            float rs = 0.f;
            #pragma unroll
            for (int nt = 0; nt < 4; nt++) {
                int col = warpN * 32 + nt * 8 + 2 * q;
                float2 v;
                float e0 = acc[mt][nt][rr * 2 + 0];
                float e1 = acc[mt][nt][rr * 2 + 1];
                float S0 = fminf(fmaxf(e0 * (1.0f / 96.0f), -60.f), 60.f);
                float S1 = fminf(fmaxf(e1 * (1.0f / 96.0f), -60.f), 60.f);
                v.x = __expf(S0);
                v.y = __expf(S1);
                if (diag) {
                    if (s0 + col     > tglob) v.x = 0.f;
                    if (s0 + col + 1 > tglob) v.y = 0.f;
                }
                rs += v.x + v.y;
                *(float2*)(Eb + (size_t)tglob * TT + s0 + col) = v;
            }
            rowsum[mt * 2 + rr] = rs;
        }
    }
    #pragma unroll
    for (int r = 0; r < 8; r++) {
        float v = rowsum[r];
        v += __shfl_xor_sync(0xffffffffu, v, 1);
        v += __shfl_xor_sync(0xffffffffu, v, 2);
        rowsum[r] = v;
    }
    if (q == 0) {
        #pragma unroll
        for (int mt = 0; mt < 4; mt++)
            #pragma unroll
            for (int rr = 0; rr < 2; rr++) {
                int row = warpM * 64 + mt * 16 + rr * 8 + g;
                part[((size_t)(b * TT + t0 + row)) * 64 + (s0 >> 5) + warpN] = rowsum[mt * 2 + rr];
            }
    }
}

// ---------------- z,s from partials ----------------
__global__ void k_zs2(const float* __restrict__ part, const float* __restrict__ a,
                      const int* __restrict__ kp, float toff,
                      float* __restrict__ z, float* __restrict__ s) {
    int row = blockIdx.x * 256 + threadIdx.x;
    int t = row & (TT - 1);
    int nb = (t >> 5) + 1;
    const float* p = part + (size_t)row * 64;
    float acc = 0.f;
    for (int j = 0; j < nb; j++) acc += p[j];
    float tv = t_of(kp, toff);
    float lam = 1.0f / (tv * tv * tv);
    float zz = fmaxf(acc * (1.0f / TT), 1e-8f);
    z[row] = zz;
    s[row] = (lam * lam * a[row]) / (zz * zz + 1e-8f);
}

// ================= force via mma.sync tf32 =================
// D[t, c] = sum_s E[t,s]*(s_t+s_s-2) * Xn[s,c]; B from XnT (col-major)
__global__ __launch_bounds__(256, 2)
void k_force_mma(const float* __restrict__ E, const float* __restrict__ XnT,
                 const float* __restrict__ sv, const int* __restrict__ kp, float toff,
                 float* __restrict__ Pupd) {
    int bc = blockIdx.x, bt = blockIdx.y, b = blockIdx.z;
    __shared__ float As[2][128 * 20];
    __shared__ float Bs[2][128 * 20];
    int tid = threadIdx.x, wid = tid >> 5, lane = tid & 31;
    int g = lane >> 2, q = lane & 3;
    int warpM = wid & 1, warpN = wid >> 1;
    int t0 = bt << 7, c0 = bc << 7;
    const float* svb = sv + b * TT;
    const float* gE = E + ((size_t)b * TT + t0) * TT;
    const float* gB = XnT + ((size_t)b * CC + c0) * TT;
    uint32_t asu = smem_u32(&As[0][0]);
    uint32_t bsu = smem_u32(&Bs[0][0]);

    int lr0 = tid >> 2, lc0 = (tid & 3) << 2;
    int lr1 = (tid + 256) >> 2, lc1 = lc0;

    float sA2[8];
    #pragma unroll
    for (int mt = 0; mt < 4; mt++) {
        sA2[mt * 2 + 0] = svb[t0 + warpM * 64 + mt * 16 + g]     - 2.0f;
        sA2[mt * 2 + 1] = svb[t0 + warpM * 64 + mt * 16 + 8 + g] - 2.0f;
    }

    float acc[4][4][4];
    #pragma unroll
    for (int i = 0; i < 4; i++)
        #pragma unroll
        for (int j = 0; j < 4; j++)
            #pragma unroll
            for (int r = 0; r < 4; r++) acc[i][j][r] = 0.f;

    const int NIT = (bt + 1) * 8;
    {
        CP16(asu + (uint32_t)(lr0 * 20 + lc0) * 4, gE + (size_t)lr0 * TT + lc0);
        CP16(asu + (uint32_t)(lr1 * 20 + lc1) * 4, gE + (size_t)lr1 * TT + lc1);
        CP16(bsu + (uint32_t)(lr0 * 20 + lc0) * 4, gB + (size_t)lr0 * TT + lc0);
        CP16(bsu + (uint32_t)(lr1 * 20 + lc1) * 4, gB + (size_t)lr1 * TT + lc1);
        CP_COMMIT();
    }
    for (int i = 0; i < NIT; i++) {
        int st = i & 1;
        if (i + 1 < NIT) {
            int kk = (i + 1) * 16;
            uint32_t so = (uint32_t)((i + 1) & 1) * 10240;
            CP16(asu + so + (uint32_t)(lr0 * 20 + lc0) * 4, gE + (size_t)lr0 * TT + kk + lc0);
            CP16(asu + so + (uint32_t)(lr1 * 20 + lc1) * 4, gE + (size_t)lr1 * TT + kk + lc1);
            CP16(bsu + so + (uint32_t)(lr0 * 20 + lc0) * 4, gB + (size_t)lr0 * TT + kk + lc0);
            CP16(bsu + so + (uint32_t)(lr1 * 20 + lc1) * 4, gB + (size_t)lr1 * TT + kk + lc1);
            CP_COMMIT();
            CP_WAIT1();
        } else {
            CP_WAIT0();
        }
        __syncthreads();
        const float* as = &As[st][0];
        const float* bsm = &Bs[st][0];
        int kkbase = i * 16;
        #pragma unroll
        for (int ks = 0; ks < 2; ks++) {
            int kb = ks * 8 + q;
            float sc0 = __ldg(&svb[kkbase + kb]);
            float sc1 = __ldg(&svb[kkbase + kb + 4]);
            uint32_t bf[4][2];
            #pragma unroll
            for (int nt = 0; nt < 4; nt++) {
                int n = warpN * 32 + nt * 8 + g;
                bf[nt][0] = __float_as_uint(bsm[n * 20 + kb]);
                bf[nt][1] = __float_as_uint(bsm[n * 20 + kb + 4]);
            }
            #pragma unroll
            for (int mt = 0; mt < 4; mt++) {
                int m = warpM * 64 + mt * 16 + g;
                uint32_t af[4];
                af[0] = to_tf32(as[m * 20 + kb]       * (sA2[mt * 2 + 0] + sc0));
                af[1] = to_tf32(as[(m + 8) * 20 + kb] * (sA2[mt * 2 + 1] + sc0));
                af[2] = to_tf32(as[m * 20 + kb + 4]       * (sA2[mt * 2 + 0] + sc1));
                af[3] = to_tf32(as[(m + 8) * 20 + kb + 4] * (sA2[mt * 2 + 1] + sc1));
                #pragma unroll
                for (int nt = 0; nt < 4; nt++) mma_tf32(acc[mt][nt], af, bf[nt]);
            }
        }
        __syncthreads();
    }

    float tv = t_of(kp, toff);
    float coef = 0.25f * tv * tv * tv / TT;   // tau * Lam / (2T)
    #pragma unroll
    for (int mt = 0; mt < 4; mt++) {
        #pragma unroll
        for (int rr = 0; rr < 2; rr++) {
            int row = warpM * 64 + mt * 16 + rr * 8 + g;
            float* Prow = Pupd + ((size_t)b * TT + t0 + row) * CC + c0;
            #pragma unroll
            for (int nt = 0; nt < 4; nt++) {
                int col = warpN * 32 + nt * 8 + 2 * q;
                float2 v = *(float2*)(Prow + col);
                v.x += coef * acc[mt][nt][rr * 2 + 0];
                v.y += coef * acc[mt][nt][rr * 2 + 1];
                *(float2*)(Prow + col) = v;
            }
        }
    }
}

// ---------------- vel ----------------
__global__ void k_vel(const float* __restrict__ Pin, const float* __restrict__ z,
                      const int* __restrict__ kp, float toff, float* __restrict__ Xupd) {
    int i = blockIdx.x * 256 + threadIdx.x;
    float tv = t_of(kp, toff);
    float lam = 1.0f / (tv * tv * tv);
    int row = i / CC;
    Xupd[i] += 0.5f * lam * Pin[i] / z[row];
}

// ---------------- rotation ----------------
__global__ void k_rotate(float* __restrict__ X, float* __restrict__ Pi,
                         float* __restrict__ bX, float* __restrict__ bPi) {
    int i = blockIdx.x * 256 + threadIdx.x;
    const float c  = -0.41614683654714241f;
    const float sn =  0.90929742682568170f;
    float x = X[i], p = Pi[i], bx = bX[i], bp = bPi[i];
    float dX = x - bx, dP = p - bp, sX = x + bx, sP = p + bp;
    X[i]   = 0.5f * (sX + c * dX + sn * dP);
    Pi[i]  = 0.5f * (sP - sn * dX + c * dP);
    bX[i]  = 0.5f * (sX - c * dX - sn * dP);
    bPi[i] = 0.5f * (sP + sn * dX - c * dP);
}

__global__ void k_copy(const float* __restrict__ src, float* __restrict__ dst) {
    int i = blockIdx.x * 256 + threadIdx.x;
    dst[i] = src[i];
}

// ---------------- launch ----------------
extern "C" void kernel_launch(void* const* d_in, const int* in_sizes, int n_in,
                              void* d_out, int out_size) {
    const float* Xk     = (const float*)d_in[0];
    const float* Pk     = (const float*)d_in[1];
    const float* ln_w   = (const float*)d_in[2];
    const float* ln_v_w = (const float*)d_in[3];
    const int*   kp     = (const int*)  d_in[4];
    float* out = (float*)d_out;

    float *X, *Pi, *bX, *bPi, *Xn, *XnT, *E, *a, *z, *s, *part;
    cudaGetSymbolAddress((void**)&X,   g_X);
    cudaGetSymbolAddress((void**)&Pi,  g_Pi);
    cudaGetSymbolAddress((void**)&bX,  g_bX);
    cudaGetSymbolAddress((void**)&bPi, g_bPi);
    cudaGetSymbolAddress((void**)&Xn,  g_Xn);
    cudaGetSymbolAddress((void**)&XnT, g_XnT);
    cudaGetSymbolAddress((void**)&E,   g_E);
    cudaGetSymbolAddress((void**)&a,   g_a);
    cudaGetSymbolAddress((void**)&z,   g_z);
    cudaGetSymbolAddress((void**)&s,   g_s);
    cudaGetSymbolAddress((void**)&part,g_part);

    const int EB = NE / 256;

    k_init<<<EB, 256>>>(Xk, Pk, kp, X, Pi, bX, bPi);

    auto phase = [&](const float* Xin, const float* Pin, float* Xupd, float* Pupd,
                     float toff, bool dovel) {
        k_ln       <<<NROW, 256>>>(Xin, ln_w, Xn, kp, 0, 0.f, 1);
        k_rowsq    <<<NROW, 256>>>(Pin, a);
        k_transpose<<<dim3(24, 64, BB), dim3(32, 8)>>>(Xn, XnT);
        k_gram_mma <<<dim3(16, 16, BB), 256>>>(Xn, E, part);
        k_zs2      <<<NROW / 256, 256>>>(part, a, kp, toff, z, s);
        k_force_mma<<<dim3(6, 16, BB), 256>>>(E, XnT, s, kp, toff, Pupd);
        if (dovel) k_vel<<<EB, 256>>>(Pin, z, kp, toff, Xupd);
    };

    phase(X,  bPi, bX, Pi,  0.0f, true);
    phase(bX, Pi,  X,  bPi, 0.5f, true);
    k_rotate<<<EB, 256>>>(X, Pi, bX, bPi);
    phase(bX, Pi,  X,  bPi, 0.5f, true);
    phase(X,  bPi, bX, Pi,  1.0f, false);

    k_copy<<<EB, 256>>>(X, out);
    k_ln  <<<NROW, 256>>>(Pi, ln_v_w, out + NE, kp, 1, 1.0f, 0);
}

// round 9
// speedup vs baseline: 4.2526x; 1.3291x over previous
#include <cuda_runtime.h>
#include <cstdint>

#define BB 4
#define TT 2048
#define CC 768
#define NROW (BB*TT)                  // 8192
#define NE   (BB*TT*CC)               // 6291456
#define STG_BYTES 20480               // per stage: A(10240)+B(10240)
#define SMEM_DYN (3*STG_BYTES)        // 61440

// ---------------- scratch ----------------
__device__ float g_X  [NE];
__device__ float g_Pi [NE];
__device__ float g_bX [NE];
__device__ float g_bPi[NE];
__device__ float g_Xn [NE];
__device__ float g_XnT[NE];
__device__ float g_E  [(size_t)BB*TT*TT];   // 64 MB
__device__ float g_a  [NROW];
__device__ float g_z  [NROW];
__device__ float g_s  [NROW];
__device__ float g_part[(size_t)NROW*64];   // per-32-col row partials

// ---------------- PTX helpers ----------------
__device__ __forceinline__ uint32_t smem_u32(const void* p){
    uint32_t a; asm("{ .reg .u64 t; cvta.to.shared.u64 t, %1; cvt.u32.u64 %0, t; }" : "=r"(a) : "l"(p));
    return a;
}
#define CP16(dst, src) \
    asm volatile("cp.async.cg.shared.global [%0], [%1], 16;" :: "r"(dst), "l"(src) : "memory")
#define CP_COMMIT() asm volatile("cp.async.commit_group;" ::: "memory")
#define CP_WAIT1()  asm volatile("cp.async.wait_group 1;" ::: "memory")

__device__ __forceinline__ uint32_t to_tf32(float f){
    uint32_t r; asm("cvt.rna.tf32.f32 %0, %1;" : "=r"(r) : "f"(f));
    return r;
}
__device__ __forceinline__ void mma_tf32(float* c, const uint32_t* a, const uint32_t* b){
    asm volatile(
        "mma.sync.aligned.m16n8k8.row.col.f32.tf32.tf32.f32 "
        "{%0,%1,%2,%3}, {%4,%5,%6,%7}, {%8,%9}, {%0,%1,%2,%3};"
        : "+f"(c[0]), "+f"(c[1]), "+f"(c[2]), "+f"(c[3])
        : "r"(a[0]), "r"(a[1]), "r"(a[2]), "r"(a[3]), "r"(b[0]), "r"(b[1]));
}
__device__ __forceinline__ void ldsm4(uint32_t* r, uint32_t addr){
    asm volatile("ldmatrix.sync.aligned.m8n8.x4.shared.b16 {%0,%1,%2,%3}, [%4];"
        : "=r"(r[0]), "=r"(r[1]), "=r"(r[2]), "=r"(r[3]) : "r"(addr));
}

__device__ __forceinline__ float blockSum256(float v) {
    __shared__ float red[8];
    int tid = threadIdx.x;
    #pragma unroll
    for (int o = 16; o; o >>= 1) v += __shfl_xor_sync(0xffffffffu, v, o);
    if ((tid & 31) == 0) red[tid >> 5] = v;
    __syncthreads();
    if (tid == 0) {
        float s = 0.f;
        #pragma unroll
        for (int i = 0; i < 8; i++) s += red[i];
        red[0] = s;
    }
    __syncthreads();
    float r = red[0];
    __syncthreads();
    return r;
}
__device__ __forceinline__ float t_of(const int* kp, float toff) {
    return 1.0f + (float)(*kp) + toff;
}

// ---------------- init ----------------
__global__ void k_init(const float* __restrict__ Xk, const float* __restrict__ Pk,
                       const int* __restrict__ kp,
                       float* __restrict__ X, float* __restrict__ Pi,
                       float* __restrict__ bX, float* __restrict__ bPi) {
    int i = blockIdx.x * 256 + threadIdx.x;
    float t = t_of(kp, 0.0f);
    float Lam = t * t * t;
    float x = Xk[i], p = Lam * Pk[i];
    X[i] = x; bX[i] = x; Pi[i] = p; bPi[i] = p;
}

// ---------------- LayerNorm + fused rowsq of Pin (phase version, tf32-rounded out) -------
__global__ void k_lnsq(const float* __restrict__ Xin, const float* __restrict__ Pin,
                       const float* __restrict__ w,
                       float* __restrict__ out, float* __restrict__ aout) {
    int row = blockIdx.x, tid = threadIdx.x;
    const float* x = Xin + (size_t)row * CC;
    const float* pp = Pin + (size_t)row * CC;
    float v[3], s = 0.f, sq = 0.f;
    #pragma unroll
    for (int i = 0; i < 3; i++) {
        v[i] = x[tid + 256 * i]; s += v[i];
        float pv = pp[tid + 256 * i]; sq += pv * pv;
    }
    s = blockSum256(s);
    float mean = s * (1.0f / CC);
    float q = 0.f;
    #pragma unroll
    for (int i = 0; i < 3; i++) { float d = v[i] - mean; q += d * d; }
    q = blockSum256(q);
    sq = blockSum256(sq);
    if (tid == 0) aout[row] = sq;
    float rstd = rsqrtf(q * (1.0f / CC) + 1e-5f);
    float* y = out + (size_t)row * CC;
    #pragma unroll
    for (int i = 0; i < 3; i++) {
        int c = tid + 256 * i;
        y[c] = __uint_as_float(to_tf32((v[i] - mean) * rstd * w[c]));
    }
}

// ---------------- LayerNorm (output version, with lam scaling) ----------------
__global__ void k_ln(const float* __restrict__ Xin, const float* __restrict__ w,
                     float* __restrict__ out, const int* __restrict__ kp, float toff) {
    int row = blockIdx.x, tid = threadIdx.x;
    float t = t_of(kp, toff);
    float scale = 1.0f / (t * t * t);
    const float* x = Xin + (size_t)row * CC;
    float v[3], s = 0.f;
    #pragma unroll
    for (int i = 0; i < 3; i++) { v[i] = scale * x[tid + 256 * i]; s += v[i]; }
    s = blockSum256(s);
    float mean = s * (1.0f / CC);
    float q = 0.f;
    #pragma unroll
    for (int i = 0; i < 3; i++) { float d = v[i] - mean; q += d * d; }
    q = blockSum256(q);
    float rstd = rsqrtf(q * (1.0f / CC) + 1e-5f);
    float* y = out + (size_t)row * CC;
    #pragma unroll
    for (int i = 0; i < 3; i++) { int c = tid + 256 * i; y[c] = (v[i] - mean) * rstd * w[c]; }
}

// ---------------- transpose Xn -> XnT [b][C][T] ----------------
__global__ void k_transpose(const float* __restrict__ Xn, float* __restrict__ XnT) {
    __shared__ float tile[32][33];
    int b = blockIdx.z;
    int c0 = blockIdx.x * 32, s0 = blockIdx.y * 32;
    int tx = threadIdx.x, ty = threadIdx.y;
    const float* src = Xn + (size_t)b * TT * CC;
    #pragma unroll
    for (int g = 0; g < 32; g += 8)
        tile[ty + g][tx] = src[(size_t)(s0 + ty + g) * CC + c0 + tx];
    __syncthreads();
    float* dst = XnT + (size_t)b * CC * TT;
    #pragma unroll
    for (int g = 0; g < 32; g += 8)
        dst[(size_t)(c0 + ty + g) * TT + s0 + tx] = tile[tx][ty + g];
}

// ================= gram via mma.sync tf32, 3-stage cp.async, ldmatrix =================
__global__ __launch_bounds__(256, 2)
void k_gram_mma(const float* __restrict__ Xn, float* __restrict__ E, float* __restrict__ part) {
    // triangular decode
    int li = blockIdx.x;
    int bt = (int)((__fsqrt_rn(8.f * li + 1.f) - 1.f) * 0.5f);
    while ((bt + 1) * (bt + 2) / 2 <= li) bt++;
    while (bt * (bt + 1) / 2 > li) bt--;
    int bs = li - bt * (bt + 1) / 2;
    int b = blockIdx.y;

    extern __shared__ char dsm[];
    uint32_t base = smem_u32(dsm);
    int tid = threadIdx.x, wid = tid >> 5, lane = tid & 31;
    int g = lane >> 2, q = lane & 3;
    int warpM = wid & 1, warpN = wid >> 1;
    int t0 = bt << 7, s0 = bs << 7;
    const float* gA = Xn + ((size_t)b * TT + t0) * CC;
    const float* gB = Xn + ((size_t)b * TT + s0) * CC;

    int lr0 = tid >> 2, lc0 = (tid & 3) << 2;
    int lr1 = lr0 + 64;
    uint32_t offA0 = (uint32_t)(lr0 * 20 + lc0) * 4;
    uint32_t offA1 = (uint32_t)(lr1 * 20 + lc0) * 4;

    // ldmatrix per-lane address pieces
    uint32_t lmA = (uint32_t)(((lane & 15) * 20 + ((lane >> 4) << 2)) * 4);
    uint32_t lmB = (uint32_t)((((lane & 7) + ((lane >> 4) << 3)) * 20 + (((lane >> 3) & 1) << 2)) * 4);

    float acc[4][4][4];
    #pragma unroll
    for (int i = 0; i < 4; i++)
        #pragma unroll
        for (int j = 0; j < 4; j++)
            #pragma unroll
            for (int r = 0; r < 4; r++) acc[i][j][r] = 0.f;

    const int NIT = CC / 16;   // 48
    auto issue = [&](int slot, int kk){
        uint32_t so = base + (uint32_t)slot * STG_BYTES;
        CP16(so + offA0,         gA + (size_t)lr0 * CC + kk + lc0);
        CP16(so + offA1,         gA + (size_t)lr1 * CC + kk + lc0);
        CP16(so + 10240 + offA0, gB + (size_t)lr0 * CC + kk + lc0);
        CP16(so + 10240 + offA1, gB + (size_t)lr1 * CC + kk + lc0);
    };
    issue(0, 0);  CP_COMMIT();
    issue(1, 16); CP_COMMIT();

    int slot = 0;
    for (int i = 0; i < NIT; i++) {
        CP_WAIT1();
        __syncthreads();
        if (i + 2 < NIT) {
            int ns = slot + 2; if (ns >= 3) ns -= 3;
            issue(ns, (i + 2) * 16);
        }
        CP_COMMIT();
        uint32_t asu = base + (uint32_t)slot * STG_BYTES;
        uint32_t bsu = asu + 10240;
        #pragma unroll
        for (int ks = 0; ks < 2; ks++) {
            uint32_t kOff = (uint32_t)(ks * 8 * 4);
            uint32_t bf[4][2];
            #pragma unroll
            for (int ntp = 0; ntp < 2; ntp++) {
                uint32_t r4[4];
                ldsm4(r4, bsu + kOff + lmB + (uint32_t)((warpN * 32 + ntp * 16) * 20 * 4));
                bf[ntp*2][0] = r4[0]; bf[ntp*2][1] = r4[1];
                bf[ntp*2+1][0] = r4[2]; bf[ntp*2+1][1] = r4[3];
            }
            #pragma unroll
            for (int mt = 0; mt < 4; mt++) {
                uint32_t af[4];
                ldsm4(af, asu + kOff + lmA + (uint32_t)((warpM * 64 + mt * 16) * 20 * 4));
                #pragma unroll
                for (int nt = 0; nt < 4; nt++) mma_tf32(acc[mt][nt], af, bf[nt]);
            }
        }
        slot++; if (slot >= 3) slot = 0;
    }

    // epilogue: clip/exp/mask, store E, fused row partial sums
    bool diag = (bs == bt);
    float* Eb = E + (size_t)b * TT * TT;
    float rowsum[8];
    #pragma unroll
    for (int mt = 0; mt < 4; mt++) {
        #pragma unroll
        for (int rr = 0; rr < 2; rr++) {
            int row = warpM * 64 + mt * 16 + rr * 8 + g;
            int tglob = t0 + row;
            float rs = 0.f;
            #pragma unroll
            for (int nt = 0; nt < 4; nt++) {
                int col = warpN * 32 + nt * 8 + 2 * q;
                float2 v;
                float S0 = fminf(fmaxf(acc[mt][nt][rr*2+0] * (1.0f/96.0f), -60.f), 60.f);
                float S1 = fminf(fmaxf(acc[mt][nt][rr*2+1] * (1.0f/96.0f), -60.f), 60.f);
                v.x = __expf(S0);
                v.y = __expf(S1);
                if (diag) {
                    if (s0 + col     > tglob) v.x = 0.f;
                    if (s0 + col + 1 > tglob) v.y = 0.f;
                }
                rs += v.x + v.y;
                *(float2*)(Eb + (size_t)tglob * TT + s0 + col) = v;
            }
            rowsum[mt * 2 + rr] = rs;
        }
    }
    #pragma unroll
    for (int r = 0; r < 8; r++) {
        float v = rowsum[r];
        v += __shfl_xor_sync(0xffffffffu, v, 1);
        v += __shfl_xor_sync(0xffffffffu, v, 2);
        rowsum[r] = v;
    }
    if (q == 0) {
        #pragma unroll
        for (int mt = 0; mt < 4; mt++)
            #pragma unroll
            for (int rr = 0; rr < 2; rr++) {
                int row = warpM * 64 + mt * 16 + rr * 8 + g;
                part[((size_t)(b * TT + t0 + row)) * 64 + (s0 >> 5) + warpN] = rowsum[mt * 2 + rr];
            }
    }
}

// ---------------- z,s from partials ----------------
__global__ void k_zs2(const float* __restrict__ part, const float* __restrict__ a,
                      const int* __restrict__ kp, float toff,
                      float* __restrict__ z, float* __restrict__ s) {
    int row = blockIdx.x * 256 + threadIdx.x;
    int t = row & (TT - 1);
    int nb = (t >> 5) + 1;
    const float* p = part + (size_t)row * 64;
    float acc = 0.f;
    for (int j = 0; j < nb; j++) acc += p[j];
    float tv = t_of(kp, toff);
    float lam = 1.0f / (tv * tv * tv);
    float zz = fmaxf(acc * (1.0f / TT), 1e-8f);
    z[row] = zz;
    s[row] = (lam * lam * a[row]) / (zz * zz + 1e-8f);
}

// ================= force via mma.sync tf32, 3-stage, ldmatrix; fused vel epilogue =======
__global__ __launch_bounds__(256, 2)
void k_force_mma(const float* __restrict__ E, const float* __restrict__ XnT,
                 const float* __restrict__ sv, const float* __restrict__ zv,
                 const float* __restrict__ Pin,
                 const int* __restrict__ kp, float toff,
                 float* __restrict__ Pupd, float* __restrict__ Xupd, int dovel) {
    int bc = blockIdx.x;
    int bt = (int)gridDim.y - 1 - (int)blockIdx.y;   // longest blocks first
    int b = blockIdx.z;
    extern __shared__ char dsm[];
    uint32_t base = smem_u32(dsm);
    int tid = threadIdx.x, wid = tid >> 5, lane = tid & 31;
    int g = lane >> 2, q = lane & 3;
    int warpM = wid & 1, warpN = wid >> 1;
    int t0 = bt << 7, c0 = bc << 7;
    const float* svb = sv + b * TT;
    const float* gE = E + ((size_t)b * TT + t0) * TT;
    const float* gB = XnT + ((size_t)b * CC + c0) * TT;

    int lr0 = tid >> 2, lc0 = (tid & 3) << 2;
    int lr1 = lr0 + 64;
    uint32_t offA0 = (uint32_t)(lr0 * 20 + lc0) * 4;
    uint32_t offA1 = (uint32_t)(lr1 * 20 + lc0) * 4;
    uint32_t lmA = (uint32_t)(((lane & 15) * 20 + ((lane >> 4) << 2)) * 4);
    uint32_t lmB = (uint32_t)((((lane & 7) + ((lane >> 4) << 3)) * 20 + (((lane >> 3) & 1) << 2)) * 4);

    float sA2[8];
    #pragma unroll
    for (int mt = 0; mt < 4; mt++) {
        sA2[mt * 2 + 0] = svb[t0 + warpM * 64 + mt * 16 + g]     - 2.0f;
        sA2[mt * 2 + 1] = svb[t0 + warpM * 64 + mt * 16 + 8 + g] - 2.0f;
    }

    float acc[4][4][4];
    #pragma unroll
    for (int i = 0; i < 4; i++)
        #pragma unroll
        for (int j = 0; j < 4; j++)
            #pragma unroll
            for (int r = 0; r < 4; r++) acc[i][j][r] = 0.f;

    const int NIT = (bt + 1) * 8;
    auto issue = [&](int slot, int kk){
        uint32_t so = base + (uint32_t)slot * STG_BYTES;
        CP16(so + offA0,         gE + (size_t)lr0 * TT + kk + lc0);
        CP16(so + offA1,         gE + (size_t)lr1 * TT + kk + lc0);
        CP16(so + 10240 + offA0, gB + (size_t)lr0 * TT + kk + lc0);
        CP16(so + 10240 + offA1, gB + (size_t)lr1 * TT + kk + lc0);
    };
    issue(0, 0);  CP_COMMIT();
    issue(1, 16); CP_COMMIT();

    int slot = 0;
    for (int i = 0; i < NIT; i++) {
        CP_WAIT1();
        __syncthreads();
        if (i + 2 < NIT) {
            int ns = slot + 2; if (ns >= 3) ns -= 3;
            issue(ns, (i + 2) * 16);
        }
        CP_COMMIT();
        uint32_t asu = base + (uint32_t)slot * STG_BYTES;
        uint32_t bsu = asu + 10240;
        int kkbase = i * 16;
        #pragma unroll
        for (int ks = 0; ks < 2; ks++) {
            uint32_t kOff = (uint32_t)(ks * 8 * 4);
            float sc0 = __ldg(&svb[kkbase + ks * 8 + q]);
            float sc1 = __ldg(&svb[kkbase + ks * 8 + 4 + q]);
            uint32_t bf[4][2];
            #pragma unroll
            for (int ntp = 0; ntp < 2; ntp++) {
                uint32_t r4[4];
                ldsm4(r4, bsu + kOff + lmB + (uint32_t)((warpN * 32 + ntp * 16) * 20 * 4));
                bf[ntp*2][0] = r4[0]; bf[ntp*2][1] = r4[1];
                bf[ntp*2+1][0] = r4[2]; bf[ntp*2+1][1] = r4[3];
            }
            #pragma unroll
            for (int mt = 0; mt < 4; mt++) {
                uint32_t e4[4];
                ldsm4(e4, asu + kOff + lmA + (uint32_t)((warpM * 64 + mt * 16) * 20 * 4));
                uint32_t af[4];
                af[0] = to_tf32(__uint_as_float(e4[0]) * (sA2[mt*2+0] + sc0));
                af[1] = to_tf32(__uint_as_float(e4[1]) * (sA2[mt*2+1] + sc0));
                af[2] = to_tf32(__uint_as_float(e4[2]) * (sA2[mt*2+0] + sc1));
                af[3] = to_tf32(__uint_as_float(e4[3]) * (sA2[mt*2+1] + sc1));
                #pragma unroll
                for (int nt = 0; nt < 4; nt++) mma_tf32(acc[mt][nt], af, bf[nt]);
            }
        }
        slot++; if (slot >= 3) slot = 0;
    }

    float tv = t_of(kp, toff);
    float coef = 0.25f * tv * tv * tv / TT;   // tau * Lam / (2T)
    #pragma unroll
    for (int mt = 0; mt < 4; mt++) {
        #pragma unroll
        for (int rr = 0; rr < 2; rr++) {
            int row = warpM * 64 + mt * 16 + rr * 8 + g;
            float* Prow = Pupd + ((size_t)b * TT + t0 + row) * CC + c0;
            #pragma unroll
            for (int nt = 0; nt < 4; nt++) {
                int col = warpN * 32 + nt * 8 + 2 * q;
                float2 v = *(float2*)(Prow + col);
                v.x += coef * acc[mt][nt][rr * 2 + 0];
                v.y += coef * acc[mt][nt][rr * 2 + 1];
                *(float2*)(Prow + col) = v;
            }
        }
    }

    // fused velocity update on the same (t, c) tile: Xupd += 0.5*lam*Pin/z[t]
    if (dovel) {
        float lam = 1.0f / (tv * tv * tv);
        const float* zb = zv + b * TT;
        for (int i4 = tid; i4 < 128 * 32; i4 += 256) {   // 128 rows x 32 float4
            int r = i4 >> 5, cc4 = (i4 & 31) << 2;
            size_t gidx = ((size_t)b * TT + t0 + r) * CC + c0 + cc4;
            float w = 0.5f * lam / zb[t0 + r];
            float4 p = *(const float4*)(Pin + gidx);
            float4 x = *(float4*)(Xupd + gidx);
            x.x += w * p.x; x.y += w * p.y; x.z += w * p.z; x.w += w * p.w;
            *(float4*)(Xupd + gidx) = x;
        }
    }
}

// ---------------- rotation ----------------
__global__ void k_rotate(float* __restrict__ X, float* __restrict__ Pi,
                         float* __restrict__ bX, float* __restrict__ bPi) {
    int i = blockIdx.x * 256 + threadIdx.x;
    const float c  = -0.41614683654714241f;
    const float sn =  0.90929742682568170f;
    float x = X[i], p = Pi[i], bx = bX[i], bp = bPi[i];
    float dX = x - bx, dP = p - bp, sX = x + bx, sP = p + bp;
    X[i]   = 0.5f * (sX + c * dX + sn * dP);
    Pi[i]  = 0.5f * (sP - sn * dX + c * dP);
    bX[i]  = 0.5f * (sX - c * dX - sn * dP);
    bPi[i] = 0.5f * (sP + sn * dX - c * dP);
}

__global__ void k_copy(const float* __restrict__ src, float* __restrict__ dst) {
    int i = blockIdx.x * 256 + threadIdx.x;
    dst[i] = src[i];
}

// ---------------- launch ----------------
extern "C" void kernel_launch(void* const* d_in, const int* in_sizes, int n_in,
                              void* d_out, int out_size) {
    const float* Xk     = (const float*)d_in[0];
    const float* Pk     = (const float*)d_in[1];
    const float* ln_w   = (const float*)d_in[2];
    const float* ln_v_w = (const float*)d_in[3];
    const int*   kp     = (const int*)  d_in[4];
    float* out = (float*)d_out;

    float *X, *Pi, *bX, *bPi, *Xn, *XnT, *E, *a, *z, *s, *part;
    cudaGetSymbolAddress((void**)&X,   g_X);
    cudaGetSymbolAddress((void**)&Pi,  g_Pi);
    cudaGetSymbolAddress((void**)&bX,  g_bX);
    cudaGetSymbolAddress((void**)&bPi, g_bPi);
    cudaGetSymbolAddress((void**)&Xn,  g_Xn);
    cudaGetSymbolAddress((void**)&XnT, g_XnT);
    cudaGetSymbolAddress((void**)&E,   g_E);
    cudaGetSymbolAddress((void**)&a,   g_a);
    cudaGetSymbolAddress((void**)&z,   g_z);
    cudaGetSymbolAddress((void**)&s,   g_s);
    cudaGetSymbolAddress((void**)&part,g_part);

    static bool attr_done = false;
    if (!attr_done) {
        cudaFuncSetAttribute(k_gram_mma,  cudaFuncAttributeMaxDynamicSharedMemorySize, SMEM_DYN);
        cudaFuncSetAttribute(k_force_mma, cudaFuncAttributeMaxDynamicSharedMemorySize, SMEM_DYN);
        attr_done = true;
    }

    const int EB = NE / 256;

    k_init<<<EB, 256>>>(Xk, Pk, kp, X, Pi, bX, bPi);

    auto phase = [&](const float* Xin, const float* Pin, float* Xupd, float* Pupd,
                     float toff, bool dovel) {
        k_lnsq     <<<NROW, 256>>>(Xin, Pin, ln_w, Xn, a);
        k_transpose<<<dim3(24, 64, BB), dim3(32, 8)>>>(Xn, XnT);
        k_gram_mma <<<dim3(136, BB), 256, SMEM_DYN>>>(Xn, E, part);
        k_zs2      <<<NROW / 256, 256>>>(part, a, kp, toff, z, s);
        k_force_mma<<<dim3(6, 16, BB), 256, SMEM_DYN>>>(E, XnT, s, z, Pin, kp, toff,
                                                        Pupd, Xupd, dovel ? 1 : 0);
    };

    phase(X,  bPi, bX, Pi,  0.0f, true);
    phase(bX, Pi,  X,  bPi, 0.5f, true);
    k_rotate<<<EB, 256>>>(X, Pi, bX, bPi);
    phase(bX, Pi,  X,  bPi, 0.5f, true);
    phase(X,  bPi, bX, Pi,  1.0f, false);

    k_copy<<<EB, 256>>>(X, out);
    k_ln  <<<NROW, 256>>>(Pi, ln_v_w, out + NE, kp, 1.0f);
}

// round 11
// speedup vs baseline: 4.9987x; 1.1754x over previous
#include <cuda_runtime.h>
#include <cstdint>

#define BB 4
#define TT 2048
#define CC 768
#define NROW (BB*TT)                  // 8192
#define NE   (BB*TT*CC)               // 6291456
#define STG_BYTES 32768               // per stage: A(16KB)+B(16KB), BK=32
#define SMEM_DYN (3*STG_BYTES)        // 98304

// ---------------- scratch ----------------
__device__ float g_X  [NE];
__device__ float g_Pi [NE];
__device__ float g_bX [NE];
__device__ float g_bPi[NE];
__device__ float g_Xn [NE];
__device__ float g_XnT[NE];
__device__ float g_E  [(size_t)BB*TT*TT];   // 64 MB
__device__ float g_a  [NROW];
__device__ float g_z  [NROW];
__device__ float g_s  [NROW];
__device__ float g_part[(size_t)NROW*64];   // per-32-col row partials

// ---------------- PTX helpers ----------------
__device__ __forceinline__ uint32_t smem_u32(const void* p){
    uint32_t a; asm("{ .reg .u64 t; cvta.to.shared.u64 t, %1; cvt.u32.u64 %0, t; }" : "=r"(a) : "l"(p));
    return a;
}
#define CP16(dst, src) \
    asm volatile("cp.async.cg.shared.global [%0], [%1], 16;" :: "r"(dst), "l"(src) : "memory")
#define CP_COMMIT() asm volatile("cp.async.commit_group;" ::: "memory")
#define CP_WAIT1()  asm volatile("cp.async.wait_group 1;" ::: "memory")

__device__ __forceinline__ uint32_t to_tf32(float f){
    uint32_t r; asm("cvt.rna.tf32.f32 %0, %1;" : "=r"(r) : "f"(f));
    return r;
}
__device__ __forceinline__ void mma_tf32(float* c, const uint32_t* a, const uint32_t* b){
    asm volatile(
        "mma.sync.aligned.m16n8k8.row.col.f32.tf32.tf32.f32 "
        "{%0,%1,%2,%3}, {%4,%5,%6,%7}, {%8,%9}, {%0,%1,%2,%3};"
        : "+f"(c[0]), "+f"(c[1]), "+f"(c[2]), "+f"(c[3])
        : "r"(a[0]), "r"(a[1]), "r"(a[2]), "r"(a[3]), "r"(b[0]), "r"(b[1]));
}
__device__ __forceinline__ void ldsm4(uint32_t* r, uint32_t addr){
    asm volatile("ldmatrix.sync.aligned.m8n8.x4.shared.b16 {%0,%1,%2,%3}, [%4];"
        : "=r"(r[0]), "=r"(r[1]), "=r"(r[2]), "=r"(r[3]) : "r"(addr));
}

__device__ __forceinline__ float blockSum256(float v) {
    __shared__ float red[8];
    int tid = threadIdx.x;
    #pragma unroll
    for (int o = 16; o; o >>= 1) v += __shfl_xor_sync(0xffffffffu, v, o);
    if ((tid & 31) == 0) red[tid >> 5] = v;
    __syncthreads();
    if (tid == 0) {
        float s = 0.f;
        #pragma unroll
        for (int i = 0; i < 8; i++) s += red[i];
        red[0] = s;
    }
    __syncthreads();
    float r = red[0];
    __syncthreads();
    return r;
}
__device__ __forceinline__ float t_of(const int* kp, float toff) {
    return 1.0f + (float)(*kp) + toff;
}

// ---------------- init ----------------
__global__ void k_init(const float* __restrict__ Xk, const float* __restrict__ Pk,
                       const int* __restrict__ kp,
                       float* __restrict__ X, float* __restrict__ Pi,
                       float* __restrict__ bX, float* __restrict__ bPi) {
    int i = blockIdx.x * 256 + threadIdx.x;
    float t = t_of(kp, 0.0f);
    float Lam = t * t * t;
    float x = Xk[i], p = Lam * Pk[i];
    X[i] = x; bX[i] = x; Pi[i] = p; bPi[i] = p;
}

// ---------------- LayerNorm + fused rowsq of Pin (tf32-rounded out) ----------------
__global__ void k_lnsq(const float* __restrict__ Xin, const float* __restrict__ Pin,
                       const float* __restrict__ w,
                       float* __restrict__ out, float* __restrict__ aout) {
    int row = blockIdx.x, tid = threadIdx.x;
    const float* x = Xin + (size_t)row * CC;
    const float* pp = Pin + (size_t)row * CC;
    float v[3], s = 0.f, sq = 0.f;
    #pragma unroll
    for (int i = 0; i < 3; i++) {
        v[i] = x[tid + 256 * i]; s += v[i];
        float pv = pp[tid + 256 * i]; sq += pv * pv;
    }
    s = blockSum256(s);
    float mean = s * (1.0f / CC);
    float q = 0.f;
    #pragma unroll
    for (int i = 0; i < 3; i++) { float d = v[i] - mean; q += d * d; }
    q = blockSum256(q);
    sq = blockSum256(sq);
    if (tid == 0) aout[row] = sq;
    float rstd = rsqrtf(q * (1.0f / CC) + 1e-5f);
    float* y = out + (size_t)row * CC;
    #pragma unroll
    for (int i = 0; i < 3; i++) {
        int c = tid + 256 * i;
        y[c] = __uint_as_float(to_tf32((v[i] - mean) * rstd * w[c]));
    }
}

// ---------------- LayerNorm (output version, with lam scaling) ----------------
__global__ void k_ln(const float* __restrict__ Xin, const float* __restrict__ w,
                     float* __restrict__ out, const int* __restrict__ kp, float toff) {
    int row = blockIdx.x, tid = threadIdx.x;
    float t = t_of(kp, toff);
    float scale = 1.0f / (t * t * t);
    const float* x = Xin + (size_t)row * CC;
    float v[3], s = 0.f;
    #pragma unroll
    for (int i = 0; i < 3; i++) { v[i] = scale * x[tid + 256 * i]; s += v[i]; }
    s = blockSum256(s);
    float mean = s * (1.0f / CC);
    float q = 0.f;
    #pragma unroll
    for (int i = 0; i < 3; i++) { float d = v[i] - mean; q += d * d; }
    q = blockSum256(q);
    float rstd = rsqrtf(q * (1.0f / CC) + 1e-5f);
    float* y = out + (size_t)row * CC;
    #pragma unroll
    for (int i = 0; i < 3; i++) { int c = tid + 256 * i; y[c] = (v[i] - mean) * rstd * w[c]; }
}

// ---------------- transpose Xn -> XnT [b][C][T] ----------------
__global__ void k_transpose(const float* __restrict__ Xn, float* __restrict__ XnT) {
    __shared__ float tile[32][33];
    int b = blockIdx.z;
    int c0 = blockIdx.x * 32, s0 = blockIdx.y * 32;
    int tx = threadIdx.x, ty = threadIdx.y;
    const float* src = Xn + (size_t)b * TT * CC;
    #pragma unroll
    for (int g = 0; g < 32; g += 8)
        tile[ty + g][tx] = src[(size_t)(s0 + ty + g) * CC + c0 + tx];
    __syncthreads();
    float* dst = XnT + (size_t)b * CC * TT;
    #pragma unroll
    for (int g = 0; g < 32; g += 8)
        dst[(size_t)(c0 + ty + g) * TT + s0 + tx] = tile[tx][ty + g];
}

// ================= gram: mma.sync tf32, BK=32, 3-stage, XOR-swizzled smem =================
__global__ __launch_bounds__(256, 2)
void k_gram_mma(const float* __restrict__ Xn, float* __restrict__ E, float* __restrict__ part) {
    int li = blockIdx.x;
    int bt = (int)((__fsqrt_rn(8.f * li + 1.f) - 1.f) * 0.5f);
    while ((bt + 1) * (bt + 2) / 2 <= li) bt++;
    while (bt * (bt + 1) / 2 > li) bt--;
    int bs = li - bt * (bt + 1) / 2;
    int b = blockIdx.y;

    extern __shared__ char dsm[];
    uint32_t base = smem_u32(dsm);
    int tid = threadIdx.x, wid = tid >> 5, lane = tid & 31;
    int g = lane >> 2, q = lane & 3;
    int warpM = wid & 1, warpN = wid >> 1;
    int t0 = bt << 7, s0 = bs << 7;
    const float* gA = Xn + ((size_t)b * TT + t0) * CC;
    const float* gB = Xn + ((size_t)b * TT + s0) * CC;

    // loader: 4 chunks per matrix per thread (128 rows x 8 16B-cols)
    int ldr[4], ldc[4]; uint32_t ldo[4];
    #pragma unroll
    for (int u = 0; u < 4; u++) {
        int idx = tid + u * 256;
        ldr[u] = idx >> 3; ldc[u] = idx & 7;
        ldo[u] = (uint32_t)(ldr[u] * 128 + ((ldc[u] ^ (ldr[u] & 7)) << 4));
    }
    // fragment address pieces (row&7 == lane&7 in both maps)
    int rowA = lane & 15;
    int rowB = (lane & 7) + ((lane >> 4) << 3);
    uint32_t swA[4], swB[4];
    #pragma unroll
    for (int ks = 0; ks < 4; ks++) {
        swA[ks] = (uint32_t)(((ks * 2 + (lane >> 4)) ^ (lane & 7)) << 4);
        swB[ks] = (uint32_t)(((ks * 2 + ((lane >> 3) & 1)) ^ (lane & 7)) << 4);
    }

    float acc[4][4][4];
    #pragma unroll
    for (int i = 0; i < 4; i++)
        #pragma unroll
        for (int j = 0; j < 4; j++)
            #pragma unroll
            for (int r = 0; r < 4; r++) acc[i][j][r] = 0.f;

    const int NIT = CC / 32;   // 24
    auto issue = [&](int slot, int kk){
        uint32_t so = base + (uint32_t)slot * STG_BYTES;
        #pragma unroll
        for (int u = 0; u < 4; u++) {
            CP16(so + ldo[u],         gA + (size_t)ldr[u] * CC + kk + ldc[u] * 4);
            CP16(so + 16384 + ldo[u], gB + (size_t)ldr[u] * CC + kk + ldc[u] * 4);
        }
    };
    issue(0, 0);  CP_COMMIT();
    issue(1, 32); CP_COMMIT();

    int slot = 0;
    for (int i = 0; i < NIT; i++) {
        CP_WAIT1();
        __syncthreads();
        if (i + 2 < NIT) {
            int ns = slot + 2; if (ns >= 3) ns -= 3;
            issue(ns, (i + 2) * 32);
        }
        CP_COMMIT();
        uint32_t asu = base + (uint32_t)slot * STG_BYTES;
        uint32_t bsu = asu + 16384;
        #pragma unroll
        for (int ks = 0; ks < 4; ks++) {
            uint32_t bf[4][2];
            #pragma unroll
            for (int ntp = 0; ntp < 2; ntp++) {
                uint32_t r4[4];
                ldsm4(r4, bsu + (uint32_t)((warpN * 32 + ntp * 16 + rowB) * 128) + swB[ks]);
                bf[ntp*2][0] = r4[0]; bf[ntp*2][1] = r4[1];
                bf[ntp*2+1][0] = r4[2]; bf[ntp*2+1][1] = r4[3];
            }
            #pragma unroll
            for (int mt = 0; mt < 4; mt++) {
                uint32_t af[4];
                ldsm4(af, asu + (uint32_t)((warpM * 64 + mt * 16 + rowA) * 128) + swA[ks]);
                #pragma unroll
                for (int nt = 0; nt < 4; nt++) mma_tf32(acc[mt][nt], af, bf[nt]);
            }
        }
        slot++; if (slot >= 3) slot = 0;
    }

    // epilogue
    bool diag = (bs == bt);
    float* Eb = E + (size_t)b * TT * TT;
    float rowsum[8];
    #pragma unroll
    for (int mt = 0; mt < 4; mt++) {
        #pragma unroll
        for (int rr = 0; rr < 2; rr++) {
            int row = warpM * 64 + mt * 16 + rr * 8 + g;
            int tglob = t0 + row;
            float rs = 0.f;
            #pragma unroll
            for (int nt = 0; nt < 4; nt++) {
                int col = warpN * 32 + nt * 8 + 2 * q;
                float2 v;
                float S0 = fminf(fmaxf(acc[mt][nt][rr*2+0] * (1.0f/96.0f), -60.f), 60.f);
                float S1 = fminf(fmaxf(acc[mt][nt][rr*2+1] * (1.0f/96.0f), -60.f), 60.f);
                v.x = __expf(S0);
                v.y = __expf(S1);
                if (diag) {
                    if (s0 + col     > tglob) v.x = 0.f;
                    if (s0 + col + 1 > tglob) v.y = 0.f;
                }
                rs += v.x + v.y;
                *(float2*)(Eb + (size_t)tglob * TT + s0 + col) = v;
            }
            rowsum[mt * 2 + rr] = rs;
        }
    }
    #pragma unroll
    for (int r = 0; r < 8; r++) {
        float v = rowsum[r];
        v += __shfl_xor_sync(0xffffffffu, v, 1);
        v += __shfl_xor_sync(0xffffffffu, v, 2);
        rowsum[r] = v;
    }
    if (q == 0) {
        #pragma unroll
        for (int mt = 0; mt < 4; mt++)
            #pragma unroll
            for (int rr = 0; rr < 2; rr++) {
                int row = warpM * 64 + mt * 16 + rr * 8 + g;
                part[((size_t)(b * TT + t0 + row)) * 64 + (s0 >> 5) + warpN] = rowsum[mt * 2 + rr];
            }
    }
}

// ---------------- z,s from partials ----------------
__global__ void k_zs2(const float* __restrict__ part, const float* __restrict__ a,
                      const int* __restrict__ kp, float toff,
                      float* __restrict__ z, float* __restrict__ s) {
    int row = blockIdx.x * 256 + threadIdx.x;
    int t = row & (TT - 1);
    int nb = (t >> 5) + 1;
    const float* p = part + (size_t)row * 64;
    float acc = 0.f;
    for (int j = 0; j < nb; j++) acc += p[j];
    float tv = t_of(kp, toff);
    float lam = 1.0f / (tv * tv * tv);
    float zz = fmaxf(acc * (1.0f / TT), 1e-8f);
    z[row] = zz;
    s[row] = (lam * lam * a[row]) / (zz * zz + 1e-8f);
}

// ================= force: mma.sync tf32, BK=32, 3-stage, swizzled; fused vel =================
__global__ __launch_bounds__(256, 2)
void k_force_mma(const float* __restrict__ E, const float* __restrict__ XnT,
                 const float* __restrict__ sv, const float* __restrict__ zv,
                 const float* __restrict__ Pin,
                 const int* __restrict__ kp, float toff,
                 float* __restrict__ Pupd, float* __restrict__ Xupd,
                 float* __restrict__ outX, int dovel) {
    int bc = blockIdx.x;
    int bt = (int)gridDim.y - 1 - (int)blockIdx.y;   // longest first
    int b = blockIdx.z;
    extern __shared__ char dsm[];
    uint32_t base = smem_u32(dsm);
    int tid = threadIdx.x, wid = tid >> 5, lane = tid & 31;
    int g = lane >> 2, q = lane & 3;
    int warpM = wid & 1, warpN = wid >> 1;
    int t0 = bt << 7, c0 = bc << 7;
    const float* svb = sv + b * TT;
    const float* gE = E + ((size_t)b * TT + t0) * TT;
    const float* gB = XnT + ((size_t)b * CC + c0) * TT;

    int ldr[4], ldc[4]; uint32_t ldo[4];
    #pragma unroll
    for (int u = 0; u < 4; u++) {
        int idx = tid + u * 256;
        ldr[u] = idx >> 3; ldc[u] = idx & 7;
        ldo[u] = (uint32_t)(ldr[u] * 128 + ((ldc[u] ^ (ldr[u] & 7)) << 4));
    }
    int rowA = lane & 15;
    int rowB = (lane & 7) + ((lane >> 4) << 3);
    uint32_t swA[4], swB[4];
    #pragma unroll
    for (int ks = 0; ks < 4; ks++) {
        swA[ks] = (uint32_t)(((ks * 2 + (lane >> 4)) ^ (lane & 7)) << 4);
        swB[ks] = (uint32_t)(((ks * 2 + ((lane >> 3) & 1)) ^ (lane & 7)) << 4);
    }

    float sA2[8];
    #pragma unroll
    for (int mt = 0; mt < 4; mt++) {
        sA2[mt * 2 + 0] = svb[t0 + warpM * 64 + mt * 16 + g]     - 2.0f;
        sA2[mt * 2 + 1] = svb[t0 + warpM * 64 + mt * 16 + 8 + g] - 2.0f;
    }

    float acc[4][4][4];
    #pragma unroll
    for (int i = 0; i < 4; i++)
        #pragma unroll
        for (int j = 0; j < 4; j++)
            #pragma unroll
            for (int r = 0; r < 4; r++) acc[i][j][r] = 0.f;

    const int NIT = (bt + 1) * 4;
    auto issue = [&](int slot, int kk){
        uint32_t so = base + (uint32_t)slot * STG_BYTES;
        #pragma unroll
        for (int u = 0; u < 4; u++) {
            CP16(so + ldo[u],         gE + (size_t)ldr[u] * TT + kk + ldc[u] * 4);
            CP16(so + 16384 + ldo[u], gB + (size_t)ldr[u] * TT + kk + ldc[u] * 4);
        }
    };
    issue(0, 0);  CP_COMMIT();
    issue(1, 32); CP_COMMIT();

    int slot = 0;
    for (int i = 0; i < NIT; i++) {
        CP_WAIT1();
        __syncthreads();
        if (i + 2 < NIT) {
            int ns = slot + 2; if (ns >= 3) ns -= 3;
            issue(ns, (i + 2) * 32);
        }
        CP_COMMIT();
        uint32_t asu = base + (uint32_t)slot * STG_BYTES;
        uint32_t bsu = asu + 16384;
        int kkbase = i * 32;
        #pragma unroll
        for (int ks = 0; ks < 4; ks++) {
            float sc0 = __ldg(&svb[kkbase + ks * 8 + q]);
            float sc1 = __ldg(&svb[kkbase + ks * 8 + 4 + q]);
            uint32_t bf[4][2];
            #pragma unroll
            for (int ntp = 0; ntp < 2; ntp++) {
                uint32_t r4[4];
                ldsm4(r4, bsu + (uint32_t)((warpN * 32 + ntp * 16 + rowB) * 128) + swB[ks]);
                bf[ntp*2][0] = r4[0]; bf[ntp*2][1] = r4[1];
                bf[ntp*2+1][0] = r4[2]; bf[ntp*2+1][1] = r4[3];
            }
            #pragma unroll
            for (int mt = 0; mt < 4; mt++) {
                uint32_t e4[4];
                ldsm4(e4, asu + (uint32_t)((warpM * 64 + mt * 16 + rowA) * 128) + swA[ks]);
                uint32_t af[4];
                af[0] = to_tf32(__uint_as_float(e4[0]) * (sA2[mt*2+0] + sc0));
                af[1] = to_tf32(__uint_as_float(e4[1]) * (sA2[mt*2+1] + sc0));
                af[2] = to_tf32(__uint_as_float(e4[2]) * (sA2[mt*2+0] + sc1));
                af[3] = to_tf32(__uint_as_float(e4[3]) * (sA2[mt*2+1] + sc1));
                #pragma unroll
                for (int nt = 0; nt < 4; nt++) mma_tf32(acc[mt][nt], af, bf[nt]);
            }
        }
        slot++; if (slot >= 3) slot = 0;
    }

    float tv = t_of(kp, toff);
    float coef = 0.25f * tv * tv * tv / TT;   // tau * Lam / (2T)
    #pragma unroll
    for (int mt = 0; mt < 4; mt++) {
        #pragma unroll
        for (int rr = 0; rr < 2; rr++) {
            int row = warpM * 64 + mt * 16 + rr * 8 + g;
            float* Prow = Pupd + ((size_t)b * TT + t0 + row) * CC + c0;
            #pragma unroll
            for (int nt = 0; nt < 4; nt++) {
                int col = warpN * 32 + nt * 8 + 2 * q;
                float2 v = *(float2*)(Prow + col);
                v.x += coef * acc[mt][nt][rr * 2 + 0];
                v.y += coef * acc[mt][nt][rr * 2 + 1];
                *(float2*)(Prow + col) = v;
            }
        }
    }

    if (dovel) {
        float lam = 1.0f / (tv * tv * tv);
        const float* zb = zv + b * TT;
        for (int i4 = tid; i4 < 128 * 32; i4 += 256) {
            int r = i4 >> 5, cc4 = (i4 & 31) << 2;
            size_t gidx = ((size_t)b * TT + t0 + r) * CC + c0 + cc4;
            float w = 0.5f * lam / zb[t0 + r];
            float4 p = *(const float4*)(Pin + gidx);
            float4 x = *(float4*)(Xupd + gidx);
            x.x += w * p.x; x.y += w * p.y; x.z += w * p.z; x.w += w * p.w;
            *(float4*)(Xupd + gidx) = x;
            if (outX) *(float4*)(outX + gidx) = x;
        }
    }
}

// ---------------- rotation ----------------
__global__ void k_rotate(float* __restrict__ X, float* __restrict__ Pi,
                         float* __restrict__ bX, float* __restrict__ bPi) {
    int i = blockIdx.x * 256 + threadIdx.x;
    const float c  = -0.41614683654714241f;
    const float sn =  0.90929742682568170f;
    float x = X[i], p = Pi[i], bx = bX[i], bp = bPi[i];
    float dX = x - bx, dP = p - bp, sX = x + bx, sP = p + bp;
    X[i]   = 0.5f * (sX + c * dX + sn * dP);
    Pi[i]  = 0.5f * (sP - sn * dX + c * dP);
    bX[i]  = 0.5f * (sX - c * dX - sn * dP);
    bPi[i] = 0.5f * (sP + sn * dX - c * dP);
}

// ---------------- launch ----------------
extern "C" void kernel_launch(void* const* d_in, const int* in_sizes, int n_in,
                              void* d_out, int out_size) {
    const float* Xk     = (const float*)d_in[0];
    const float* Pk     = (const float*)d_in[1];
    const float* ln_w   = (const float*)d_in[2];
    const float* ln_v_w = (const float*)d_in[3];
    const int*   kp     = (const int*)  d_in[4];
    float* out = (float*)d_out;

    float *X, *Pi, *bX, *bPi, *Xn, *XnT, *E, *a, *z, *s, *part;
    cudaGetSymbolAddress((void**)&X,   g_X);
    cudaGetSymbolAddress((void**)&Pi,  g_Pi);
    cudaGetSymbolAddress((void**)&bX,  g_bX);
    cudaGetSymbolAddress((void**)&bPi, g_bPi);
    cudaGetSymbolAddress((void**)&Xn,  g_Xn);
    cudaGetSymbolAddress((void**)&XnT, g_XnT);
    cudaGetSymbolAddress((void**)&E,   g_E);
    cudaGetSymbolAddress((void**)&a,   g_a);
    cudaGetSymbolAddress((void**)&z,   g_z);
    cudaGetSymbolAddress((void**)&s,   g_s);
    cudaGetSymbolAddress((void**)&part,g_part);

    static bool attr_done = false;
    if (!attr_done) {
        cudaFuncSetAttribute(k_gram_mma,  cudaFuncAttributeMaxDynamicSharedMemorySize, SMEM_DYN);
        cudaFuncSetAttribute(k_force_mma, cudaFuncAttributeMaxDynamicSharedMemorySize, SMEM_DYN);
        attr_done = true;
    }

    const int EB = NE / 256;

    k_init<<<EB, 256>>>(Xk, Pk, kp, X, Pi, bX, bPi);

    auto phase = [&](const float* Xin, const float* Pin, float* Xupd, float* Pupd,
                     float toff, bool dovel, float* outX) {
        k_lnsq     <<<NROW, 256>>>(Xin, Pin, ln_w, Xn, a);
        k_transpose<<<dim3(24, 64, BB), dim3(32, 8)>>>(Xn, XnT);
        k_gram_mma <<<dim3(136, BB), 256, SMEM_DYN>>>(Xn, E, part);
        k_zs2      <<<NROW / 256, 256>>>(part, a, kp, toff, z, s);
        k_force_mma<<<dim3(6, 16, BB), 256, SMEM_DYN>>>(E, XnT, s, z, Pin, kp, toff,
                                                        Pupd, Xupd, outX, dovel ? 1 : 0);
    };

    phase(X,  bPi, bX, Pi,  0.0f, true,  nullptr);
    phase(bX, Pi,  X,  bPi, 0.5f, true,  nullptr);
    k_rotate<<<EB, 256>>>(X, Pi, bX, bPi);
    phase(bX, Pi,  X,  bPi, 0.5f, true,  out);      // final X lands in out here
    phase(X,  bPi, bX, Pi,  1.0f, false, nullptr);

    k_ln<<<NROW, 256>>>(Pi, ln_v_w, out + NE, kp, 1.0f);
}